// round 8
// baseline (speedup 1.0000x reference)
#include <cuda_runtime.h>
#include <cstdint>

// Problem constants
#define Bb 2
#define Nn 100000
#define Ff 64
#define Ee 800000
#define EO 16
#define NO 64

// Scratch (device globals — no allocation allowed)
__device__ float g_P[Bb * Nn * 32];    // [b][n][0:16]=x·W1, [16:32]=x·W2
__device__ float g_agg[Bb * Nn * 16];  // aggregation buffer

// ---------------------------------------------------------------------------
// Packed fp32x2 helpers (Blackwell sm_100+)
// ---------------------------------------------------------------------------
__device__ __forceinline__ unsigned long long pack2(float a, float b) {
    unsigned long long r;
    asm("mov.b64 %0, {%1, %2};" : "=l"(r) : "f"(a), "f"(b));
    return r;
}
__device__ __forceinline__ float2 unpack2(unsigned long long v) {
    float2 r;
    asm("mov.b64 {%0, %1}, %2;" : "=f"(r.x), "=f"(r.y) : "l"(v));
    return r;
}
__device__ __forceinline__ unsigned long long fma2(unsigned long long a,
                                                   unsigned long long b,
                                                   unsigned long long c) {
    unsigned long long d;
    asm("fma.rn.f32x2 %0, %1, %2, %3;" : "=l"(d) : "l"(a), "l"(b), "l"(c));
    return d;
}

// ---------------------------------------------------------------------------
// MUFU sigmoid: 2 MUFU + 2 FMA-pipe ops; MUFU pipe otherwise idle.
// ---------------------------------------------------------------------------
__device__ __forceinline__ float sigmoid_mufu(float x) {
    float e, r;
    asm("ex2.approx.ftz.f32 %0, %1;" : "=f"(e) : "f"(x * -1.4426950408889634f));
    asm("rcp.approx.ftz.f32 %0, %1;" : "=f"(r) : "f"(1.0f + e));
    return r;
}

// ---------------------------------------------------------------------------
// K1: zero g_agg, then P[b,n,j] = sum_k x[b,n,k] * W1/W2[k,j].
// Combines the two independently-proven K1 fixes:
//  - round 7: 2-deep LDG prefetch (removed the MLP-starvation wall, -10us)
//  - round 6: half-warp-per-node mapping (8 LDS/node instead of 16; halved
//    L1 pressure, which is the binder now that the latency wall is gone).
// Lanes 0-15 own node0, 16-31 own node1; each lane computes BOTH W1 and W2
// column (lane&15) of its node; one ld.shared.v2.b64 per kk serves both
// halves (conflict degree 2 = free on the 128B crossbar).
// ---------------------------------------------------------------------------
__global__ __launch_bounds__(128) void k1_precompute(
    const float* __restrict__ x, const float* __restrict__ W_e) {
    __shared__ float xs[4][2][128];   // [warp][buf][node0 row | node1 row]

    const int tid = blockIdx.x * blockDim.x + threadIdx.x;
    const int nth = gridDim.x * blockDim.x;

    // Zero the aggregation buffer (vectorized)
    const float4 z4 = make_float4(0.f, 0.f, 0.f, 0.f);
    for (int i = tid; i < (Bb * Nn * 16) / 4; i += nth)
        ((float4*)g_agg)[i] = z4;

    const int lane = threadIdx.x & 31;
    const int winb = threadIdx.x >> 5;
    const int half = lane >> 4;        // 0: node0, 1: node1
    const int col  = lane & 15;        // owned output column (W1 and W2)

    // Weights for this column, packed by k-pairs.
    unsigned long long wa2[32], wb2[32];
#pragma unroll
    for (int k = 0; k < 32; k++) {
        wa2[k] = pack2(__ldg(W_e + (2 * k) * EO + col),
                       __ldg(W_e + (2 * k + 1) * EO + col));
        wb2[k] = pack2(__ldg(W_e + (64 + 2 * k) * EO + col),
                       __ldg(W_e + (64 + 2 * k + 1) * EO + col));
    }

    const uint32_t sb0 = (uint32_t)__cvta_generic_to_shared(&xs[winb][0][0]);
    const uint32_t sb1 = (uint32_t)__cvta_generic_to_shared(&xs[winb][1][0]);
    const uint32_t hoff = (uint32_t)half * 256;   // my node's row offset

    const int NP     = (Bb * Nn) / 2;
    const int warpId = tid >> 5;
    const int nwarps = nth >> 5;

    // 2-deep prefetch pipeline (tail prefetches clamp; values never used).
    float4 xv0 = ((const float4*)(x + (size_t)warpId * 128))[lane];
    {
        const int pr1 = warpId + nwarps;
        const int c1  = pr1 < NP ? pr1 : NP - 1;
        float4 xv1 = ((const float4*)(x + (size_t)c1 * 128))[lane];

        int p = 0;
        for (int pair = warpId; pair < NP; pair += nwarps) {
            ((float4*)(p ? xs[winb][1] : xs[winb][0]))[lane] = xv0;
            __syncwarp();
            xv0 = xv1;
            const int pr2 = pair + 2 * nwarps;
            const int c2  = pr2 < NP ? pr2 : NP - 1;
            xv1 = ((const float4*)(x + (size_t)c2 * 128))[lane];  // 2 ahead

            const uint32_t sb = (p ? sb1 : sb0) + hoff;
            unsigned long long accA0 = 0ull, accA1 = 0ull;  // W1 col
            unsigned long long accB0 = 0ull, accB1 = 0ull;  // W2 col
#pragma unroll
            for (int kk = 0; kk < 16; kk++) {
                unsigned long long a0, a1;
                asm volatile("ld.shared.v2.b64 {%0, %1}, [%2];"
                             : "=l"(a0), "=l"(a1) : "r"(sb + kk * 16));
                accA0 = fma2(a0, wa2[2 * kk],     accA0);
                accA1 = fma2(a1, wa2[2 * kk + 1], accA1);
                accB0 = fma2(a0, wb2[2 * kk],     accB0);
                accB1 = fma2(a1, wb2[2 * kk + 1], accB1);
            }

            const float2 sA0 = unpack2(accA0), sA1 = unpack2(accA1);
            const float2 sB0 = unpack2(accB0), sB1 = unpack2(accB1);
            const int node = pair * 2 + half;
            g_P[(size_t)node * 32 + col]      = (sA0.x + sA0.y) + (sA1.x + sA1.y);
            g_P[(size_t)node * 32 + 16 + col] = (sB0.x + sB0.y) + (sB1.x + sB1.y);
            p ^= 1;
        }
    }
}

// ---------------------------------------------------------------------------
// K2: BOTH batches fused per edge. Thread quad q of edge e loads (s,t,wv)
// ONCE, gathers P for batch0 AND batch1 (4 independent 16B nc loads),
// computes 8 sigmoids, issues 4 red.v4. Halves the index-load stream and
// doubles per-iteration MLP vs the per-batch loop; RED count is the floor
// and unchanged. (K2 proved insensitive to prefetch in round 7 ->
// throughput-bound; this cuts ops instead of adding overlap.)
// ---------------------------------------------------------------------------
__global__ __launch_bounds__(256) void k2_edges(
    const int* __restrict__ esrc, const int* __restrict__ etgt,
    const float* __restrict__ ew, const float* __restrict__ W_e,
    const float* __restrict__ b_e) {
    const int tid0 = blockIdx.x * blockDim.x + threadIdx.x;
    const int nth  = gridDim.x * blockDim.x;   // multiple of 4 -> q invariant
    const int q    = tid0 & 3;

    const float4 w3 = ((const float4*)(W_e + 128 * EO))[q];  // ew row
    const float4 bq = ((const float4*)b_e)[q];

    const float* P0 = g_P;
    const float* P1 = g_P + (size_t)Nn * 32;
    float* agg0     = g_agg;
    float* agg1     = g_agg + (size_t)Nn * 16;

    for (int gid = tid0; gid < Ee * 4; gid += nth) {
        const int e = gid >> 2;

        const int   s  = __ldg(esrc + e);
        const int   t  = __ldg(etgt + e);
        const float wv = __ldg(ew + e);

        // 4 independent gathers (2 per batch).
        const float4 p1a = __ldg((const float4*)(P0 + (size_t)s * 32 + q * 4));
        const float4 p2a = __ldg((const float4*)(P0 + (size_t)t * 32 + 16 + q * 4));
        const float4 p1b = __ldg((const float4*)(P1 + (size_t)s * 32 + q * 4));
        const float4 p2b = __ldg((const float4*)(P1 + (size_t)t * 32 + 16 + q * 4));

        const float cx = fmaf(wv, w3.x, bq.x);
        const float cy = fmaf(wv, w3.y, bq.y);
        const float cz = fmaf(wv, w3.z, bq.z);
        const float cw = fmaf(wv, w3.w, bq.w);

        float4 ha, hb;
        ha.x = sigmoid_mufu(p1a.x + p2a.x + cx);
        ha.y = sigmoid_mufu(p1a.y + p2a.y + cy);
        ha.z = sigmoid_mufu(p1a.z + p2a.z + cz);
        ha.w = sigmoid_mufu(p1a.w + p2a.w + cw);
        hb.x = sigmoid_mufu(p1b.x + p2b.x + cx);
        hb.y = sigmoid_mufu(p1b.y + p2b.y + cy);
        hb.z = sigmoid_mufu(p1b.z + p2b.z + cz);
        hb.w = sigmoid_mufu(p1b.w + p2b.w + cw);

        float* t0 = agg0 + (size_t)t * 16 + q * 4;
        float* s0 = agg0 + (size_t)s * 16 + q * 4;
        float* t1 = agg1 + (size_t)t * 16 + q * 4;
        float* s1 = agg1 + (size_t)s * 16 + q * 4;
        asm volatile("red.global.add.v4.f32 [%0], {%1,%2,%3,%4};"
                     :: "l"(t0), "f"(ha.x), "f"(ha.y), "f"(ha.z), "f"(ha.w) : "memory");
        asm volatile("red.global.add.v4.f32 [%0], {%1,%2,%3,%4};"
                     :: "l"(s0), "f"(-ha.x), "f"(-ha.y), "f"(-ha.z), "f"(-ha.w) : "memory");
        asm volatile("red.global.add.v4.f32 [%0], {%1,%2,%3,%4};"
                     :: "l"(t1), "f"(hb.x), "f"(hb.y), "f"(hb.z), "f"(hb.w) : "memory");
        asm volatile("red.global.add.v4.f32 [%0], {%1,%2,%3,%4};"
                     :: "l"(s1), "f"(-hb.x), "f"(-hb.y), "f"(-hb.z), "f"(-hb.w) : "memory");
    }
}

// ---------------------------------------------------------------------------
// K3: out[b,n,:] = sigmoid(agg[b,n,:16] @ W_n[16,64] + b_n). Warp per node;
// lane owns cols {lane, lane+32}; packed fma2; MUFU sigmoid.
// ---------------------------------------------------------------------------
__global__ __launch_bounds__(256) void k3_nodes(
    const float* __restrict__ W_n, const float* __restrict__ b_n,
    float* __restrict__ out) {
    const int lane = threadIdx.x & 31;

    unsigned long long wA2[8], wB2[8];
#pragma unroll
    for (int j = 0; j < 8; j++) {
        wA2[j] = pack2(__ldg(W_n + (2 * j) * NO + lane),
                       __ldg(W_n + (2 * j + 1) * NO + lane));
        wB2[j] = pack2(__ldg(W_n + (2 * j) * NO + lane + 32),
                       __ldg(W_n + (2 * j + 1) * NO + lane + 32));
    }
    const float bA = __ldg(b_n + lane);
    const float bB = __ldg(b_n + lane + 32);

    const int tid    = blockIdx.x * blockDim.x + threadIdx.x;
    const int warpId = tid >> 5;
    const int nwarps = (gridDim.x * blockDim.x) >> 5;

    for (int node = warpId; node < Bb * Nn; node += nwarps) {
        const float* ag = g_agg + (size_t)node * 16;
        unsigned long long a[8];
#pragma unroll
        for (int j = 0; j < 4; j++)
            asm volatile("ld.global.nc.v2.b64 {%0, %1}, [%2];"
                         : "=l"(a[2 * j]), "=l"(a[2 * j + 1])
                         : "l"(ag + 4 * j));

        unsigned long long accA = 0ull, accB = 0ull;
#pragma unroll
        for (int j = 0; j < 8; j++) {
            accA = fma2(a[j], wA2[j], accA);
            accB = fma2(a[j], wB2[j], accB);
        }
        float2 sA = unpack2(accA), sB = unpack2(accB);
        out[(size_t)node * NO + lane]      = sigmoid_mufu(bA + sA.x + sA.y);
        out[(size_t)node * NO + lane + 32] = sigmoid_mufu(bB + sB.x + sB.y);
    }
}

// ---------------------------------------------------------------------------
extern "C" void kernel_launch(void* const* d_in, const int* in_sizes, int n_in,
                              void* d_out, int out_size) {
    const float* x    = (const float*)d_in[0];
    const int*   esrc = (const int*)d_in[1];
    const int*   etgt = (const int*)d_in[2];
    const float* ew   = (const float*)d_in[3];
    const float* W_e  = (const float*)d_in[4];
    const float* b_e  = (const float*)d_in[5];
    const float* W_n  = (const float*)d_in[6];
    const float* b_n  = (const float*)d_in[7];
    float* out = (float*)d_out;

    k1_precompute<<<148 * 16, 128>>>(x, W_e);
    k2_edges<<<148 * 8, 256>>>(esrc, etgt, ew, W_e, b_e);
    k3_nodes<<<148 * 8, 256>>>(W_n, b_n, out);
}